// round 3
// baseline (speedup 1.0000x reference)
#include <cuda_runtime.h>

#define NN 50000
#define NE 800000
#define NF 256
#define NH 64
#define NC 40
#define EPSR 0.3f
#define NB_SCAN ((NN + 255) / 256)   // 196

// ---- device scratch ----
__device__ __align__(128) int   g_deg[NN];
__device__ __align__(128) int   g_cnt[NN];
__device__ __align__(128) int   g_fill[NN];
__device__ __align__(128) float g_nd[NN];
__device__ __align__(128) float g_cinv[NN];
__device__ __align__(128) float g_s1[NN];
__device__ __align__(128) float g_s2[NN];
__device__ __align__(128) int   g_ptr[NN + 1];
__device__ __align__(128) int   g_bsum[NB_SCAN];
__device__ __align__(128) int   g_src[NE];
__device__ __align__(128) int   g_dstS[NE];
__device__ __align__(128) float g_ndeS[NE];
__device__ __align__(128) float g_nrm[NE];
__device__ __align__(128) float g_h[NN * NH];
__device__ __align__(128) float g_h2[NN * NH];
__device__ __align__(128) float g_raw[NN * NH];
__device__ __align__(128) float g_W1t[NF * NH];

__global__ void k_zero_nodes() {
    int i = blockIdx.x * blockDim.x + threadIdx.x;
    if (i < NN) { g_deg[i] = 0; g_cnt[i] = 0; g_fill[i] = 0; }
}

// degree/count histograms (edge_index is int32: jax default x64-disabled)
__global__ void k_count(const int* __restrict__ ei) {
    int e = blockIdx.x * blockDim.x + threadIdx.x;
    if (e >= NE) return;
    atomicAdd(&g_deg[ei[e]], 1);        // row = source
    atomicAdd(&g_cnt[ei[NE + e]], 1);   // col = target
}

__global__ void k_nodeprep() {
    int i = blockIdx.x * blockDim.x + threadIdx.x;
    if (i >= NN) return;
    int d = g_deg[i]; if (d < 1) d = 1;
    g_nd[i] = rsqrtf((float)d);
    int c = g_cnt[i]; if (c < 1) c = 1;
    g_cinv[i] = 1.0f / (float)c;
}

// ---- exclusive prefix scan of g_cnt ----
__global__ void k_scan1() {
    __shared__ int sh[256];
    int i = blockIdx.x * 256 + threadIdx.x;
    int v = (i < NN) ? g_cnt[i] : 0;
    sh[threadIdx.x] = v;
    __syncthreads();
    for (int off = 1; off < 256; off <<= 1) {
        int t = (threadIdx.x >= off) ? sh[threadIdx.x - off] : 0;
        __syncthreads();
        sh[threadIdx.x] += t;
        __syncthreads();
    }
    if (i < NN) g_ptr[i] = sh[threadIdx.x] - v;   // exclusive
    if (threadIdx.x == 255) g_bsum[blockIdx.x] = sh[255];
}

__global__ void k_scan2() {
    __shared__ int sh[256];
    int i = threadIdx.x;
    int v = (i < NB_SCAN) ? g_bsum[i] : 0;
    sh[i] = v;
    __syncthreads();
    for (int off = 1; off < 256; off <<= 1) {
        int t = (i >= off) ? sh[i - off] : 0;
        __syncthreads();
        sh[i] += t;
        __syncthreads();
    }
    if (i < NB_SCAN) g_bsum[i] = sh[i] - v;       // exclusive block offsets
}

__global__ void k_scan3() {
    int i = blockIdx.x * 256 + threadIdx.x;
    if (i < NN) g_ptr[i] += g_bsum[blockIdx.x];
    if (i == 0) g_ptr[NN] = NE;
}

// CSR bucketing by target node (within-segment order irrelevant for sums)
__global__ void k_bucket(const int* __restrict__ ei) {
    int e = blockIdx.x * blockDim.x + threadIdx.x;
    if (e >= NE) return;
    int r = ei[e];
    int c = ei[NE + e];
    int p = g_ptr[c] + atomicAdd(&g_fill[c], 1);
    g_src[p]  = r;
    g_dstS[p] = c;
    g_ndeS[p] = g_nd[r] * g_nd[c];
}

// W1 [NH, NF] -> W1t [NF, NH]
__global__ void k_w1t(const float* __restrict__ W1) {
    int idx = blockIdx.x * blockDim.x + threadIdx.x;
    if (idx >= NF * NH) return;
    int k = idx >> 6;
    int j = idx & 63;
    g_W1t[idx] = W1[j * NF + k];
}

// h = relu(x @ W1^T + b1)
__global__ void k_gemm1(const float* __restrict__ x, const float* __restrict__ b1) {
    int t = blockIdx.x * blockDim.x + threadIdx.x;
    int n = t >> 6;
    int j = t & 63;
    if (n >= NN) return;
    float acc = b1[j];
    const float4* xr = (const float4*)(x + (size_t)n * NF);
#pragma unroll 8
    for (int k4 = 0; k4 < NF / 4; k4++) {
        float4 xv = xr[k4];
        int k = k4 * 4;
        acc += xv.x * g_W1t[(k    ) * NH + j];
        acc += xv.y * g_W1t[(k + 1) * NH + j];
        acc += xv.z * g_W1t[(k + 2) * NH + j];
        acc += xv.w * g_W1t[(k + 3) * NH + j];
    }
    float hv = fmaxf(acc, 0.0f);
    g_h[n * NH + j]   = hv;
    g_raw[n * NH + j] = hv;
}

// per-node gate scalars: s1 = h·w_a, s2 = h·w_b
__global__ void k_scalars(const float* __restrict__ hin, const float* __restrict__ gw, int l) {
    int n = blockIdx.x * blockDim.x + threadIdx.x;
    if (n >= NN) return;
    const float4* hr  = (const float4*)(hin + n * NH);
    const float4* wav = (const float4*)(gw + l * 2 * NH);
    const float4* wbv = (const float4*)(gw + l * 2 * NH + NH);
    float s1 = 0.0f, s2 = 0.0f;
#pragma unroll
    for (int q = 0; q < NH / 4; q++) {
        float4 hv = hr[q], a = wav[q], b = wbv[q];
        s1 += hv.x * a.x + hv.y * a.y + hv.z * a.z + hv.w * a.w;
        s2 += hv.x * b.x + hv.y * b.y + hv.z * b.z + hv.w * b.w;
    }
    g_s1[n] = s1;
    g_s2[n] = s2;
}

// per-slot gate norm, CSR order
__global__ void k_norm(const float* __restrict__ gbp, int l) {
    int p = blockIdx.x * blockDim.x + threadIdx.x;
    if (p >= NE) return;
    float g = tanhf(g_s1[g_src[p]] + g_s2[g_dstS[p]] + gbp[l]);
    g_nrm[p] = g * g_ndeS[p];
}

// aggregation + residual update: 64 threads per node
__global__ void k_agg(const float* __restrict__ hin, float* __restrict__ hout) {
    int t = blockIdx.x * blockDim.x + threadIdx.x;
    int n = t >> 6;
    int j = t & 63;
    if (n >= NN) return;
    int b = g_ptr[n];
    int e = g_ptr[n + 1];
    float acc = 0.0f, ns = 0.0f;
    int p = b;
    for (; p + 1 < e; p += 2) {
        float nm0 = g_nrm[p];
        float nm1 = g_nrm[p + 1];
        int   r0  = g_src[p];
        int   r1  = g_src[p + 1];
        float h0  = hin[r0 * NH + j];
        float h1  = hin[r1 * NH + j];
        ns  += nm0 + nm1;
        acc += nm0 * h0 + nm1 * h1;
    }
    if (p < e) {
        float nm = g_nrm[p];
        ns  += nm;
        acc += nm * hin[g_src[p] * NH + j];
    }
    float hv = hin[n * NH + j];
    hout[n * NH + j] = EPSR * g_raw[n * NH + j] + (acc + hv * ns) * g_cinv[n];
}

// logits + log_softmax
__global__ void k_out(const float* __restrict__ hin, const float* __restrict__ W2,
                      const float* __restrict__ b2, float* __restrict__ out) {
    int n = blockIdx.x * blockDim.x + threadIdx.x;
    if (n >= NN) return;
    float hreg[NH];
    const float4* hr = (const float4*)(hin + n * NH);
#pragma unroll
    for (int q = 0; q < NH / 4; q++) {
        float4 v = hr[q];
        hreg[q * 4 + 0] = v.x; hreg[q * 4 + 1] = v.y;
        hreg[q * 4 + 2] = v.z; hreg[q * 4 + 3] = v.w;
    }
    float logit[NC];
    float m = -1e30f;
#pragma unroll
    for (int c = 0; c < NC; c++) {
        const float* w = W2 + c * NH;
        float acc = b2[c];
#pragma unroll
        for (int jj = 0; jj < NH; jj++) acc += hreg[jj] * w[jj];
        logit[c] = acc;
        m = fmaxf(m, acc);
    }
    float s = 0.0f;
#pragma unroll
    for (int c = 0; c < NC; c++) s += expf(logit[c] - m);
    float lse = m + logf(s);
    float* o = out + (size_t)n * NC;
#pragma unroll
    for (int c = 0; c < NC; c++) o[c] = logit[c] - lse;
}

extern "C" void kernel_launch(void* const* d_in, const int* in_sizes, int n_in,
                              void* d_out, int out_size) {
    const float* x  = (const float*)d_in[0];
    const int*   ei = (const int*)d_in[1];    // int32: jax x64 disabled
    const float* W1 = (const float*)d_in[2];
    const float* b1 = (const float*)d_in[3];
    const float* W2 = (const float*)d_in[4];
    const float* b2 = (const float*)d_in[5];
    const float* gw = (const float*)d_in[6];
    const float* gb = (const float*)d_in[7];
    float* out = (float*)d_out;

    float* hA; float* hB;
    cudaGetSymbolAddress((void**)&hA, g_h);
    cudaGetSymbolAddress((void**)&hB, g_h2);

    const int B = 256;
    k_zero_nodes<<<(NN + B - 1) / B, B>>>();
    k_count<<<(NE + B - 1) / B, B>>>(ei);
    k_nodeprep<<<(NN + B - 1) / B, B>>>();
    k_scan1<<<NB_SCAN, 256>>>();
    k_scan2<<<1, 256>>>();
    k_scan3<<<NB_SCAN, 256>>>();
    k_bucket<<<(NE + B - 1) / B, B>>>(ei);
    k_w1t<<<(NF * NH + B - 1) / B, B>>>(W1);
    k_gemm1<<<(NN * NH + B - 1) / B, B>>>(x, b1);

    float* cur = hA; float* nxt = hB;
    for (int l = 0; l < 2; l++) {
        k_scalars<<<(NN + B - 1) / B, B>>>(cur, gw, l);
        k_norm<<<(NE + B - 1) / B, B>>>(gb, l);
        k_agg<<<(NN * NH + B - 1) / B, B>>>(cur, nxt);
        float* tmp = cur; cur = nxt; nxt = tmp;
    }

    k_out<<<(NN + B - 1) / B, B>>>(cur, W2, b2, out);
}

// round 4
// speedup vs baseline: 1.0735x; 1.0735x over previous
#include <cuda_runtime.h>

#define NN 50000
#define NE 800000
#define NF 256
#define NH 64
#define NC 40
#define EPSR 0.3f
#define NB_SCAN ((NN + 255) / 256)   // 196

// ---- device scratch ----
__device__ __align__(128) int       g_deg[NN];
__device__ __align__(128) int       g_cnt[NN];
__device__ __align__(128) int       g_fill[NN];
__device__ __align__(128) float     g_nd[NN];
__device__ __align__(128) float     g_cinv[NN];
__device__ __align__(128) float     g_s1[NN];
__device__ __align__(128) float     g_s2[NN];
__device__ __align__(128) int       g_ptr[NN + 1];
__device__ __align__(128) int       g_bsum[NB_SCAN];
__device__ __align__(128) long long g_ed[NE];       // packed {src, nde}
__device__ __align__(128) float     g_h[NN * NH];
__device__ __align__(128) float     g_h2[NN * NH];
__device__ __align__(128) float     g_raw[NN * NH];
__device__ __align__(128) float     g_W1t[NF * NH];

// zeros + W1 transpose, one launch
__global__ void k_prep(const float* __restrict__ W1) {
    int i = blockIdx.x * blockDim.x + threadIdx.x;
    if (i < NN) {
        g_deg[i] = 0; g_cnt[i] = 0; g_fill[i] = 0;
        g_s1[i] = 0.0f; g_s2[i] = 0.0f;
    }
    if (i < NF * NH) {
        int k = i >> 6, j = i & 63;
        g_W1t[i] = W1[j * NF + k];
    }
}

// degree/count histograms (edge_index is int32)
__global__ void k_count(const int* __restrict__ ei) {
    int e = blockIdx.x * blockDim.x + threadIdx.x;
    if (e >= NE) return;
    atomicAdd(&g_deg[ei[e]], 1);        // row = source
    atomicAdd(&g_cnt[ei[NE + e]], 1);   // col = target
}

// block scan of cnt + nodeprep (nd, cinv) fused
__global__ void k_scan1() {
    __shared__ int sh[256];
    int i = blockIdx.x * 256 + threadIdx.x;
    int v = (i < NN) ? g_cnt[i] : 0;
    sh[threadIdx.x] = v;
    __syncthreads();
    for (int off = 1; off < 256; off <<= 1) {
        int t = (threadIdx.x >= off) ? sh[threadIdx.x - off] : 0;
        __syncthreads();
        sh[threadIdx.x] += t;
        __syncthreads();
    }
    if (i < NN) {
        g_ptr[i] = sh[threadIdx.x] - v;   // exclusive
        int d = g_deg[i]; if (d < 1) d = 1;
        g_nd[i] = rsqrtf((float)d);
        int c = v; if (c < 1) c = 1;
        g_cinv[i] = 1.0f / (float)c;
    }
    if (threadIdx.x == 255) g_bsum[blockIdx.x] = sh[255];
}

__global__ void k_scan2() {
    __shared__ int sh[256];
    int i = threadIdx.x;
    int v = (i < NB_SCAN) ? g_bsum[i] : 0;
    sh[i] = v;
    __syncthreads();
    for (int off = 1; off < 256; off <<= 1) {
        int t = (i >= off) ? sh[i - off] : 0;
        __syncthreads();
        sh[i] += t;
        __syncthreads();
    }
    if (i < NB_SCAN) g_bsum[i] = sh[i] - v;
}

__global__ void k_scan3() {
    int i = blockIdx.x * 256 + threadIdx.x;
    if (i < NN) g_ptr[i] += g_bsum[blockIdx.x];
    if (i == 0) g_ptr[NN] = NE;
}

// CSR bucketing by target; pack {src, nd[src]*nd[col]} into 8B
__global__ void k_bucket(const int* __restrict__ ei) {
    int e = blockIdx.x * blockDim.x + threadIdx.x;
    if (e >= NE) return;
    int r = ei[e];
    int c = ei[NE + e];
    int p = g_ptr[c] + atomicAdd(&g_fill[c], 1);
    float nde = g_nd[r] * g_nd[c];
    g_ed[p] = (long long)(unsigned int)r |
              ((long long)__float_as_int(nde) << 32);
}

// h = relu(x@W1^T + b1); epilogue accumulates layer-0 gate scalars
__global__ void k_gemm1(const float* __restrict__ x, const float* __restrict__ b1,
                        const float* __restrict__ gw) {
    int t = blockIdx.x * blockDim.x + threadIdx.x;
    int n = t >> 6;
    int j = t & 63;
    if (n >= NN) return;
    float acc = b1[j];
    const float4* xr = (const float4*)(x + (size_t)n * NF);
#pragma unroll 8
    for (int k4 = 0; k4 < NF / 4; k4++) {
        float4 xv = xr[k4];
        int k = k4 * 4;
        acc += xv.x * g_W1t[(k    ) * NH + j];
        acc += xv.y * g_W1t[(k + 1) * NH + j];
        acc += xv.z * g_W1t[(k + 2) * NH + j];
        acc += xv.w * g_W1t[(k + 3) * NH + j];
    }
    float hv = fmaxf(acc, 0.0f);
    g_h[n * NH + j]   = hv;
    g_raw[n * NH + j] = hv;
    // layer-0 gate scalars: warp covers 32 consecutive j's of one node
    float p1 = hv * gw[j];
    float p2 = hv * gw[NH + j];
#pragma unroll
    for (int off = 16; off > 0; off >>= 1) {
        p1 += __shfl_xor_sync(0xffffffff, p1, off);
        p2 += __shfl_xor_sync(0xffffffff, p2, off);
    }
    if ((t & 31) == 0) {
        atomicAdd(&g_s1[n], p1);
        atomicAdd(&g_s2[n], p2);
    }
}

// warp-per-node aggregation: fused gate-norm + mean-agg + residual update
// + optional next-layer gate-scalar epilogue
template <bool COMPUTE_S>
__global__ void k_agg(const float* __restrict__ hin, float* __restrict__ hout,
                      const float* __restrict__ gw_next,
                      const float* __restrict__ gbp, int l) {
    __shared__ int   s_src[8][32];
    __shared__ float s_nrm[8][32];
    int w    = threadIdx.x >> 5;
    int lane = threadIdx.x & 31;
    int n    = blockIdx.x * 8 + w;
    if (n >= NN) return;

    int b = g_ptr[n];
    int e = g_ptr[n + 1];
    float s2n = g_s2[n] + gbp[l];
    float2 acc = make_float2(0.0f, 0.0f);
    float  ns  = 0.0f;
    int j2 = lane * 2;

    for (int base = b; base < e; base += 32) {
        int p = base + lane;
        int r = 0; float nm = 0.0f;
        if (p < e) {
            long long ev = g_ed[p];
            r = (int)ev;
            float nde = __int_as_float((int)(ev >> 32));
            nm = tanhf(g_s1[r] + s2n) * nde;
        }
        s_src[w][lane] = r;
        s_nrm[w][lane] = nm;
        __syncwarp();
        int cnt = e - base; if (cnt > 32) cnt = 32;
        int ii = 0;
        for (; ii + 4 <= cnt; ii += 4) {
            int   r0 = s_src[w][ii    ], r1 = s_src[w][ii + 1];
            int   r2 = s_src[w][ii + 2], r3 = s_src[w][ii + 3];
            float n0 = s_nrm[w][ii    ], n1 = s_nrm[w][ii + 1];
            float n2 = s_nrm[w][ii + 2], n3 = s_nrm[w][ii + 3];
            float2 h0 = *(const float2*)(hin + r0 * NH + j2);
            float2 h1 = *(const float2*)(hin + r1 * NH + j2);
            float2 h2 = *(const float2*)(hin + r2 * NH + j2);
            float2 h3 = *(const float2*)(hin + r3 * NH + j2);
            acc.x += n0 * h0.x + n1 * h1.x + n2 * h2.x + n3 * h3.x;
            acc.y += n0 * h0.y + n1 * h1.y + n2 * h2.y + n3 * h3.y;
            ns    += n0 + n1 + n2 + n3;
        }
        for (; ii < cnt; ii++) {
            int   r0 = s_src[w][ii];
            float n0 = s_nrm[w][ii];
            float2 h0 = *(const float2*)(hin + r0 * NH + j2);
            acc.x += n0 * h0.x;
            acc.y += n0 * h0.y;
            ns    += n0;
        }
        __syncwarp();
    }

    float2 hself = *(const float2*)(hin   + n * NH + j2);
    float2 rawv  = *(const float2*)(g_raw + n * NH + j2);
    float ci = g_cinv[n];
    float2 ho;
    ho.x = EPSR * rawv.x + (acc.x + hself.x * ns) * ci;
    ho.y = EPSR * rawv.y + (acc.y + hself.y * ns) * ci;
    *(float2*)(hout + n * NH + j2) = ho;

    if (COMPUTE_S) {
        float p1 = ho.x * gw_next[j2] + ho.y * gw_next[j2 + 1];
        float p2 = ho.x * gw_next[NH + j2] + ho.y * gw_next[NH + j2 + 1];
#pragma unroll
        for (int off = 16; off > 0; off >>= 1) {
            p1 += __shfl_xor_sync(0xffffffff, p1, off);
            p2 += __shfl_xor_sync(0xffffffff, p2, off);
        }
        if (lane == 0) { g_s1[n] = p1; g_s2[n] = p2; }
    }
}

// logits + log_softmax
__global__ void k_out(const float* __restrict__ hin, const float* __restrict__ W2,
                      const float* __restrict__ b2, float* __restrict__ out) {
    int n = blockIdx.x * blockDim.x + threadIdx.x;
    if (n >= NN) return;
    float hreg[NH];
    const float4* hr = (const float4*)(hin + n * NH);
#pragma unroll
    for (int q = 0; q < NH / 4; q++) {
        float4 v = hr[q];
        hreg[q * 4 + 0] = v.x; hreg[q * 4 + 1] = v.y;
        hreg[q * 4 + 2] = v.z; hreg[q * 4 + 3] = v.w;
    }
    float logit[NC];
    float m = -1e30f;
#pragma unroll
    for (int c = 0; c < NC; c++) {
        const float* wv = W2 + c * NH;
        float acc = b2[c];
#pragma unroll
        for (int jj = 0; jj < NH; jj++) acc += hreg[jj] * wv[jj];
        logit[c] = acc;
        m = fmaxf(m, acc);
    }
    float s = 0.0f;
#pragma unroll
    for (int c = 0; c < NC; c++) s += expf(logit[c] - m);
    float lse = m + logf(s);
    float* o = out + (size_t)n * NC;
#pragma unroll
    for (int c = 0; c < NC; c++) o[c] = logit[c] - lse;
}

extern "C" void kernel_launch(void* const* d_in, const int* in_sizes, int n_in,
                              void* d_out, int out_size) {
    const float* x  = (const float*)d_in[0];
    const int*   ei = (const int*)d_in[1];
    const float* W1 = (const float*)d_in[2];
    const float* b1 = (const float*)d_in[3];
    const float* W2 = (const float*)d_in[4];
    const float* b2 = (const float*)d_in[5];
    const float* gw = (const float*)d_in[6];
    const float* gb = (const float*)d_in[7];
    float* out = (float*)d_out;

    float* hA; float* hB;
    cudaGetSymbolAddress((void**)&hA, g_h);
    cudaGetSymbolAddress((void**)&hB, g_h2);

    const int B = 256;
    k_prep<<<(NN + B - 1) / B, B>>>(W1);                    // 0
    k_count<<<(NE + B - 1) / B, B>>>(ei);                   // 1
    k_scan1<<<NB_SCAN, 256>>>();                            // 2
    k_scan2<<<1, 256>>>();                                  // 3
    k_scan3<<<NB_SCAN, 256>>>();                            // 4
    k_bucket<<<(NE + B - 1) / B, B>>>(ei);                  // 5 (ncu -s 5 target)
    k_gemm1<<<(NN * NH + B - 1) / B, B>>>(x, b1, gw);       // 6

    // layer 0: agg + compute layer-1 gate scalars
    k_agg<true><<<(NN + 7) / 8, 256>>>(hA, hB, gw + 2 * NH, gb, 0);   // 7
    // layer 1
    k_agg<false><<<(NN + 7) / 8, 256>>>(hB, hA, gw, gb, 1);           // 8

    k_out<<<(NN + B - 1) / B, B>>>(hA, W2, b2, out);        // 9
}

// round 5
// speedup vs baseline: 1.6950x; 1.5790x over previous
#include <cuda_runtime.h>

#define NN 50000
#define NE 800000
#define NF 256
#define NH 64
#define NC 40
#define EPSR 0.3f
#define NB_SCAN ((NN + 255) / 256)   // 196
#define MT 64                         // gemm M-tile (nodes per block)
#define KT 32                         // gemm K-chunk

// ---- device scratch ----
__device__ __align__(128) int       g_deg[NN];
__device__ __align__(128) int       g_cnt[NN];
__device__ __align__(128) int       g_fill[NN];
__device__ __align__(128) float     g_nd[NN];
__device__ __align__(128) float     g_cinv[NN];
__device__ __align__(128) float     g_s1[NN];
__device__ __align__(128) float     g_s2[NN];
__device__ __align__(128) int       g_ptr[NN + 1];
__device__ __align__(128) int       g_bsum[NB_SCAN];
__device__ __align__(128) long long g_ed[NE];       // packed {src, nde}
__device__ __align__(128) float     g_h[NN * NH];
__device__ __align__(128) float     g_h2[NN * NH];
__device__ __align__(128) float     g_raw[NN * NH];
__device__ __align__(128) float     g_W1t[NF * NH];

// zeros + W1 transpose
__global__ void k_prep(const float* __restrict__ W1) {
    int i = blockIdx.x * blockDim.x + threadIdx.x;
    if (i < NN) { g_deg[i] = 0; g_cnt[i] = 0; }
    if (i < NF * NH) {
        int k = i >> 6, j = i & 63;
        g_W1t[i] = W1[j * NF + k];
    }
}

__global__ void k_count(const int* __restrict__ ei) {
    int e = blockIdx.x * blockDim.x + threadIdx.x;
    if (e >= NE) return;
    atomicAdd(&g_deg[ei[e]], 1);        // row = source
    atomicAdd(&g_cnt[ei[NE + e]], 1);   // col = target
}

// block scan of cnt + nodeprep fused
__global__ void k_scan1() {
    __shared__ int sh[256];
    int i = blockIdx.x * 256 + threadIdx.x;
    int v = (i < NN) ? g_cnt[i] : 0;
    sh[threadIdx.x] = v;
    __syncthreads();
    for (int off = 1; off < 256; off <<= 1) {
        int t = (threadIdx.x >= off) ? sh[threadIdx.x - off] : 0;
        __syncthreads();
        sh[threadIdx.x] += t;
        __syncthreads();
    }
    if (i < NN) {
        g_ptr[i] = sh[threadIdx.x] - v;   // exclusive
        int d = g_deg[i]; if (d < 1) d = 1;
        g_nd[i] = rsqrtf((float)d);
        int c = v; if (c < 1) c = 1;
        g_cinv[i] = 1.0f / (float)c;
    }
    if (threadIdx.x == 255) g_bsum[blockIdx.x] = sh[255];
}

__global__ void k_scan2() {
    __shared__ int sh[256];
    int i = threadIdx.x;
    int v = (i < NB_SCAN) ? g_bsum[i] : 0;
    sh[i] = v;
    __syncthreads();
    for (int off = 1; off < 256; off <<= 1) {
        int t = (i >= off) ? sh[i - off] : 0;
        __syncthreads();
        sh[i] += t;
        __syncthreads();
    }
    if (i < NB_SCAN) g_bsum[i] = sh[i] - v;
}

// finalize ptr and seed fill cursors
__global__ void k_scan3() {
    int i = blockIdx.x * 256 + threadIdx.x;
    if (i < NN) {
        int v = g_ptr[i] + g_bsum[blockIdx.x];
        g_ptr[i]  = v;
        g_fill[i] = v;   // bucket uses fill as the slot cursor directly
    }
    if (i == 0) g_ptr[NN] = NE;
}

// CSR bucketing by target; pack {src, nd[src]*nd[col]}
__global__ void k_bucket(const int* __restrict__ ei) {
    int e = blockIdx.x * blockDim.x + threadIdx.x;
    if (e >= NE) return;
    int r = ei[e];
    int c = ei[NE + e];
    int p = atomicAdd(&g_fill[c], 1);
    float nde = g_nd[r] * g_nd[c];
    g_ed[p] = (long long)(unsigned int)r |
              ((long long)__float_as_int(nde) << 32);
}

// Tiled GEMM: h = relu(x @ W1^T + b1), 64x64x256 per block, 4x4 micro-tile.
// Epilogue: layer-0 gate scalars s1=h.w_a, s2=h.w_b (deterministic smem tree).
__global__ __launch_bounds__(256) void k_gemm1(const float* __restrict__ x,
                                               const float* __restrict__ b1,
                                               const float* __restrict__ gw) {
    __shared__ float xs[KT][MT + 4];   // [k][m], padded row = 68 floats (16B-aligned)
    __shared__ float ws[KT * NH];      // [k][j] flat

    int tid = threadIdx.x;
    int tx = tid & 15;                 // j block: j0 = tx*4
    int ty = tid >> 4;                 // m block: m0 = ty*4
    int nb = blockIdx.x * MT;

    float acc[4][4] = {{0}};

    int lm = tid >> 2;                 // 0..63: m for x load
    int kq = tid & 3;                  // 0..3 : k-octet for x load
    int xrow = nb + lm; if (xrow >= NN) xrow = NN - 1;   // clamp (stores guarded)
    const float* xr = x + (size_t)xrow * NF;

    for (int k0 = 0; k0 < NF; k0 += KT) {
        // stage x tile transposed: xs[k][m]
        float4 a0 = *(const float4*)(xr + k0 + kq * 8);
        float4 a1 = *(const float4*)(xr + k0 + kq * 8 + 4);
        xs[kq * 8 + 0][lm] = a0.x; xs[kq * 8 + 1][lm] = a0.y;
        xs[kq * 8 + 2][lm] = a0.z; xs[kq * 8 + 3][lm] = a0.w;
        xs[kq * 8 + 4][lm] = a1.x; xs[kq * 8 + 5][lm] = a1.y;
        xs[kq * 8 + 6][lm] = a1.z; xs[kq * 8 + 7][lm] = a1.w;
        // stage W tile: flat copy (coalesced float4)
        const float4* wsrc = (const float4*)(g_W1t + k0 * NH);
        float4* wdst = (float4*)ws;
        wdst[tid]       = wsrc[tid];
        wdst[tid + 256] = wsrc[tid + 256];
        __syncthreads();
#pragma unroll
        for (int kk = 0; kk < KT; kk++) {
            float4 av = *(const float4*)&xs[kk][ty * 4];
            float4 bv = *(const float4*)&ws[kk * NH + tx * 4];
            acc[0][0] += av.x * bv.x; acc[0][1] += av.x * bv.y;
            acc[0][2] += av.x * bv.z; acc[0][3] += av.x * bv.w;
            acc[1][0] += av.y * bv.x; acc[1][1] += av.y * bv.y;
            acc[1][2] += av.y * bv.z; acc[1][3] += av.y * bv.w;
            acc[2][0] += av.z * bv.x; acc[2][1] += av.z * bv.y;
            acc[2][2] += av.z * bv.z; acc[2][3] += av.z * bv.w;
            acc[3][0] += av.w * bv.x; acc[3][1] += av.w * bv.y;
            acc[3][2] += av.w * bv.z; acc[3][3] += av.w * bv.w;
        }
        __syncthreads();
    }

    // epilogue: bias + relu + store, and gate-scalar partials
    float4 bb = *(const float4*)(b1 + tx * 4);
    float4 wa = *(const float4*)(gw + tx * 4);
    float4 wb = *(const float4*)(gw + NH + tx * 4);

    // reuse smem for deterministic per-node reduction: [64 rows][17]
    float (*s1p)[17] = (float(*)[17])&xs[0][0];
    float (*s2p)[17] = (float(*)[17])&ws[0];

#pragma unroll
    for (int i = 0; i < 4; i++) {
        int n = nb + ty * 4 + i;
        float4 hv;
        hv.x = fmaxf(acc[i][0] + bb.x, 0.0f);
        hv.y = fmaxf(acc[i][1] + bb.y, 0.0f);
        hv.z = fmaxf(acc[i][2] + bb.z, 0.0f);
        hv.w = fmaxf(acc[i][3] + bb.w, 0.0f);
        if (n < NN) {
            *(float4*)(g_h   + n * NH + tx * 4) = hv;
            *(float4*)(g_raw + n * NH + tx * 4) = hv;
        }
        s1p[ty * 4 + i][tx] = hv.x * wa.x + hv.y * wa.y + hv.z * wa.z + hv.w * wa.w;
        s2p[ty * 4 + i][tx] = hv.x * wb.x + hv.y * wb.y + hv.z * wb.z + hv.w * wb.w;
    }
    __syncthreads();
    if (tid < MT) {
        int n = nb + tid;
        if (n < NN) {
            float s1 = 0.0f, s2 = 0.0f;
#pragma unroll
            for (int q = 0; q < 16; q++) { s1 += s1p[tid][q]; s2 += s2p[tid][q]; }
            g_s1[n] = s1;
            g_s2[n] = s2;
        }
    }
}

// warp-per-node aggregation: fused gate-norm + mean-agg + residual
// + optional next-layer gate-scalar epilogue
template <bool COMPUTE_S>
__global__ void k_agg(const float* __restrict__ hin, float* __restrict__ hout,
                      const float* __restrict__ gw_next,
                      const float* __restrict__ gbp, int l) {
    __shared__ int   s_src[8][32];
    __shared__ float s_nrm[8][32];
    int w    = threadIdx.x >> 5;
    int lane = threadIdx.x & 31;
    int n    = blockIdx.x * 8 + w;
    if (n >= NN) return;

    int b = g_ptr[n];
    int e = g_ptr[n + 1];
    float s2n = g_s2[n] + gbp[l];
    float2 acc = make_float2(0.0f, 0.0f);
    float  ns  = 0.0f;
    int j2 = lane * 2;

    for (int base = b; base < e; base += 32) {
        int p = base + lane;
        int r = 0; float nm = 0.0f;
        if (p < e) {
            long long ev = g_ed[p];
            r = (int)ev;
            float nde = __int_as_float((int)(ev >> 32));
            nm = tanhf(g_s1[r] + s2n) * nde;
        }
        s_src[w][lane] = r;
        s_nrm[w][lane] = nm;
        __syncwarp();
        int cnt = e - base; if (cnt > 32) cnt = 32;
        int ii = 0;
        for (; ii + 4 <= cnt; ii += 4) {
            int   r0 = s_src[w][ii    ], r1 = s_src[w][ii + 1];
            int   r2 = s_src[w][ii + 2], r3 = s_src[w][ii + 3];
            float n0 = s_nrm[w][ii    ], n1 = s_nrm[w][ii + 1];
            float n2 = s_nrm[w][ii + 2], n3 = s_nrm[w][ii + 3];
            float2 h0 = *(const float2*)(hin + r0 * NH + j2);
            float2 h1 = *(const float2*)(hin + r1 * NH + j2);
            float2 h2 = *(const float2*)(hin + r2 * NH + j2);
            float2 h3 = *(const float2*)(hin + r3 * NH + j2);
            acc.x += n0 * h0.x + n1 * h1.x + n2 * h2.x + n3 * h3.x;
            acc.y += n0 * h0.y + n1 * h1.y + n2 * h2.y + n3 * h3.y;
            ns    += n0 + n1 + n2 + n3;
        }
        for (; ii < cnt; ii++) {
            int   r0 = s_src[w][ii];
            float n0 = s_nrm[w][ii];
            float2 h0 = *(const float2*)(hin + r0 * NH + j2);
            acc.x += n0 * h0.x;
            acc.y += n0 * h0.y;
            ns    += n0;
        }
        __syncwarp();
    }

    float2 hself = *(const float2*)(hin   + n * NH + j2);
    float2 rawv  = *(const float2*)(g_raw + n * NH + j2);
    float ci = g_cinv[n];
    float2 ho;
    ho.x = EPSR * rawv.x + (acc.x + hself.x * ns) * ci;
    ho.y = EPSR * rawv.y + (acc.y + hself.y * ns) * ci;
    *(float2*)(hout + n * NH + j2) = ho;

    if (COMPUTE_S) {
        float p1 = ho.x * gw_next[j2] + ho.y * gw_next[j2 + 1];
        float p2 = ho.x * gw_next[NH + j2] + ho.y * gw_next[NH + j2 + 1];
#pragma unroll
        for (int off = 16; off > 0; off >>= 1) {
            p1 += __shfl_xor_sync(0xffffffff, p1, off);
            p2 += __shfl_xor_sync(0xffffffff, p2, off);
        }
        if (lane == 0) { g_s1[n] = p1; g_s2[n] = p2; }
    }
}

// logits + log_softmax
__global__ void k_out(const float* __restrict__ hin, const float* __restrict__ W2,
                      const float* __restrict__ b2, float* __restrict__ out) {
    int n = blockIdx.x * blockDim.x + threadIdx.x;
    if (n >= NN) return;
    float hreg[NH];
    const float4* hr = (const float4*)(hin + n * NH);
#pragma unroll
    for (int q = 0; q < NH / 4; q++) {
        float4 v = hr[q];
        hreg[q * 4 + 0] = v.x; hreg[q * 4 + 1] = v.y;
        hreg[q * 4 + 2] = v.z; hreg[q * 4 + 3] = v.w;
    }
    float logit[NC];
    float m = -1e30f;
#pragma unroll
    for (int c = 0; c < NC; c++) {
        const float* wv = W2 + c * NH;
        float acc = b2[c];
#pragma unroll
        for (int jj = 0; jj < NH; jj++) acc += hreg[jj] * wv[jj];
        logit[c] = acc;
        m = fmaxf(m, acc);
    }
    float s = 0.0f;
#pragma unroll
    for (int c = 0; c < NC; c++) s += expf(logit[c] - m);
    float lse = m + logf(s);
    float* o = out + (size_t)n * NC;
#pragma unroll
    for (int c = 0; c < NC; c++) o[c] = logit[c] - lse;
}

extern "C" void kernel_launch(void* const* d_in, const int* in_sizes, int n_in,
                              void* d_out, int out_size) {
    const float* x  = (const float*)d_in[0];
    const int*   ei = (const int*)d_in[1];
    const float* W1 = (const float*)d_in[2];
    const float* b1 = (const float*)d_in[3];
    const float* W2 = (const float*)d_in[4];
    const float* b2 = (const float*)d_in[5];
    const float* gw = (const float*)d_in[6];
    const float* gb = (const float*)d_in[7];
    float* out = (float*)d_out;

    float* hA; float* hB;
    cudaGetSymbolAddress((void**)&hA, g_h);
    cudaGetSymbolAddress((void**)&hB, g_h2);

    const int B = 256;
    k_prep<<<(NN + B - 1) / B, B>>>(W1);
    k_count<<<(NE + B - 1) / B, B>>>(ei);
    k_scan1<<<NB_SCAN, 256>>>();
    k_scan2<<<1, 256>>>();
    k_scan3<<<NB_SCAN, 256>>>();
    k_bucket<<<(NE + B - 1) / B, B>>>(ei);
    k_gemm1<<<(NN + MT - 1) / MT, 256>>>(x, b1, gw);

    // layer 0: agg + compute layer-1 gate scalars
    k_agg<true><<<(NN + 7) / 8, 256>>>(hA, hB, gw + 2 * NH, gb, 0);
    // layer 1
    k_agg<false><<<(NN + 7) / 8, 256>>>(hB, hA, gw, gb, 1);

    k_out<<<(NN + B - 1) / B, B>>>(hA, W2, b2, out);
}

// round 6
// speedup vs baseline: 2.2330x; 1.3174x over previous
#include <cuda_runtime.h>

#define NN 50000
#define NE 800000
#define NF 256
#define NH 64
#define NC 40
#define EPSR 0.3f
#define NB_SCAN ((NN + 255) / 256)   // 196
#define MT 64                         // gemm M-tile
#define KT 32                         // gemm K-chunk
#define AGG_WPB 16                    // warps (nodes) per agg block

// ---- device scratch ----
__device__ __align__(128) int   g_deg[NN];
__device__ __align__(128) int   g_cnt[NN];
__device__ __align__(128) int   g_fill[NN];
__device__ __align__(128) float g_ci[NN];         // nd[n]/max(cnt,1)
__device__ __align__(128) float g_s2[NN];
__device__ __align__(128) float g_snA[2 * NN];    // {s1_layer0, nd} interleaved
__device__ __align__(128) float g_snB[2 * NN];    // {s1_layer1, nd} interleaved
__device__ __align__(128) int   g_ptr[NN + 1];
__device__ __align__(128) int   g_bsum[NB_SCAN];
__device__ __align__(128) int   g_srcA[NE];       // CSR src per slot
__device__ __align__(128) float g_h[NN * NH];     // layer-0 h == raw (never overwritten)
__device__ __align__(128) float g_h2[NN * NH];    // layer-1 input
__device__ __align__(128) float g_W1t[NF * NH];

__global__ void k_zero() {
    int i = blockIdx.x * blockDim.x + threadIdx.x;
    if (i < NN) { g_deg[i] = 0; g_cnt[i] = 0; }
}

__global__ void k_w1t(const float* __restrict__ W1) {
    int i = blockIdx.x * blockDim.x + threadIdx.x;
    if (i < NF * NH) {
        int k = i >> 6, j = i & 63;
        g_W1t[i] = W1[j * NF + k];
    }
}

__global__ void k_count(const int* __restrict__ ei) {
    int e = blockIdx.x * blockDim.x + threadIdx.x;
    if (e >= NE) return;
    atomicAdd(&g_deg[ei[e]], 1);        // row = source
    atomicAdd(&g_cnt[ei[NE + e]], 1);   // col = target
}

// block scan of cnt + node prep (nd, ci, sn.y) fused
__global__ void k_scan1() {
    __shared__ int sh[256];
    int i = blockIdx.x * 256 + threadIdx.x;
    int v = (i < NN) ? g_cnt[i] : 0;
    sh[threadIdx.x] = v;
    __syncthreads();
    for (int off = 1; off < 256; off <<= 1) {
        int t = (threadIdx.x >= off) ? sh[threadIdx.x - off] : 0;
        __syncthreads();
        sh[threadIdx.x] += t;
        __syncthreads();
    }
    if (i < NN) {
        g_ptr[i] = sh[threadIdx.x] - v;   // exclusive (pre-offset)
        int d = g_deg[i]; if (d < 1) d = 1;
        float nd = rsqrtf((float)d);
        int c = v; if (c < 1) c = 1;
        g_ci[i] = nd / (float)c;
        g_snA[2 * i + 1] = nd;
        g_snB[2 * i + 1] = nd;
    }
    if (threadIdx.x == 255) g_bsum[blockIdx.x] = sh[255];
}

__global__ void k_scan2() {
    __shared__ int sh[256];
    int i = threadIdx.x;
    int v = (i < NB_SCAN) ? g_bsum[i] : 0;
    sh[i] = v;
    __syncthreads();
    for (int off = 1; off < 256; off <<= 1) {
        int t = (i >= off) ? sh[i - off] : 0;
        __syncthreads();
        sh[i] += t;
        __syncthreads();
    }
    if (i < NB_SCAN) g_bsum[i] = sh[i] - v;
}

__global__ void k_scan3() {
    int i = blockIdx.x * 256 + threadIdx.x;
    if (i < NN) {
        int v = g_ptr[i] + g_bsum[blockIdx.x];
        g_ptr[i]  = v;
        g_fill[i] = v;
    }
    if (i == 0) g_ptr[NN] = NE;
}

// CSR bucketing: just the source index (nd folded into per-node tables)
__global__ void k_bucket(const int* __restrict__ ei) {
    int e = blockIdx.x * blockDim.x + threadIdx.x;
    if (e >= NE) return;
    int r = ei[e];
    int c = ei[NE + e];
    int p = atomicAdd(&g_fill[c], 1);
    g_srcA[p] = r;
}

// Tiled GEMM: h = relu(x @ W1^T + b1); epilogue: layer-0 gate scalars.
__global__ __launch_bounds__(256) void k_gemm1(const float* __restrict__ x,
                                               const float* __restrict__ b1,
                                               const float* __restrict__ gw) {
    __shared__ float xs[KT][MT + 4];
    __shared__ float ws[KT * NH];

    int tid = threadIdx.x;
    int tx = tid & 15;
    int ty = tid >> 4;
    int nb = blockIdx.x * MT;

    float acc[4][4] = {{0}};

    int lm = tid >> 2;
    int kq = tid & 3;
    int xrow = nb + lm; if (xrow >= NN) xrow = NN - 1;
    const float* xr = x + (size_t)xrow * NF;

    for (int k0 = 0; k0 < NF; k0 += KT) {
        float4 a0 = *(const float4*)(xr + k0 + kq * 8);
        float4 a1 = *(const float4*)(xr + k0 + kq * 8 + 4);
        xs[kq * 8 + 0][lm] = a0.x; xs[kq * 8 + 1][lm] = a0.y;
        xs[kq * 8 + 2][lm] = a0.z; xs[kq * 8 + 3][lm] = a0.w;
        xs[kq * 8 + 4][lm] = a1.x; xs[kq * 8 + 5][lm] = a1.y;
        xs[kq * 8 + 6][lm] = a1.z; xs[kq * 8 + 7][lm] = a1.w;
        const float4* wsrc = (const float4*)(g_W1t + k0 * NH);
        float4* wdst = (float4*)ws;
        wdst[tid]       = wsrc[tid];
        wdst[tid + 256] = wsrc[tid + 256];
        __syncthreads();
#pragma unroll
        for (int kk = 0; kk < KT; kk++) {
            float4 av = *(const float4*)&xs[kk][ty * 4];
            float4 bv = *(const float4*)&ws[kk * NH + tx * 4];
            acc[0][0] += av.x * bv.x; acc[0][1] += av.x * bv.y;
            acc[0][2] += av.x * bv.z; acc[0][3] += av.x * bv.w;
            acc[1][0] += av.y * bv.x; acc[1][1] += av.y * bv.y;
            acc[1][2] += av.y * bv.z; acc[1][3] += av.y * bv.w;
            acc[2][0] += av.z * bv.x; acc[2][1] += av.z * bv.y;
            acc[2][2] += av.z * bv.z; acc[2][3] += av.z * bv.w;
            acc[3][0] += av.w * bv.x; acc[3][1] += av.w * bv.y;
            acc[3][2] += av.w * bv.z; acc[3][3] += av.w * bv.w;
        }
        __syncthreads();
    }

    float4 bb = *(const float4*)(b1 + tx * 4);
    float4 wa = *(const float4*)(gw + tx * 4);
    float4 wb = *(const float4*)(gw + NH + tx * 4);

    float (*s1p)[17] = (float(*)[17])&xs[0][0];
    float (*s2p)[17] = (float(*)[17])&ws[0];

#pragma unroll
    for (int i = 0; i < 4; i++) {
        int n = nb + ty * 4 + i;
        float4 hv;
        hv.x = fmaxf(acc[i][0] + bb.x, 0.0f);
        hv.y = fmaxf(acc[i][1] + bb.y, 0.0f);
        hv.z = fmaxf(acc[i][2] + bb.z, 0.0f);
        hv.w = fmaxf(acc[i][3] + bb.w, 0.0f);
        if (n < NN) *(float4*)(g_h + n * NH + tx * 4) = hv;
        s1p[ty * 4 + i][tx] = hv.x * wa.x + hv.y * wa.y + hv.z * wa.z + hv.w * wa.w;
        s2p[ty * 4 + i][tx] = hv.x * wb.x + hv.y * wb.y + hv.z * wb.z + hv.w * wb.w;
    }
    __syncthreads();
    if (tid < MT) {
        int n = nb + tid;
        if (n < NN) {
            float s1 = 0.0f, s2 = 0.0f;
#pragma unroll
            for (int q = 0; q < 16; q++) { s1 += s1p[tid][q]; s2 += s2p[tid][q]; }
            g_snA[2 * n] = s1;
            g_s2[n] = s2;
        }
    }
}

// layer-0 aggregation (warp per node) + layer-1 gate scalars into the B buffers
__global__ __launch_bounds__(32 * AGG_WPB) void k_agg0(const float* __restrict__ gw_next,
                                                       const float* __restrict__ gb) {
    __shared__ int   s_src[AGG_WPB][32];
    __shared__ float s_nrm[AGG_WPB][32];
    int w    = threadIdx.x >> 5;
    int lane = threadIdx.x & 31;
    int n    = blockIdx.x * AGG_WPB + w;
    if (n >= NN) return;

    int b = g_ptr[n];
    int e = g_ptr[n + 1];
    float s2n = g_s2[n] + gb[0];
    float2 acc = make_float2(0.0f, 0.0f);
    float  ns  = 0.0f;
    int j2 = lane * 2;

    for (int base = b; base < e; base += 32) {
        int p = base + lane;
        int r = 0; float nm = 0.0f;
        if (p < e) {
            r = g_srcA[p];
            float2 sn = *(const float2*)(g_snA + 2 * r);
            nm = tanhf(sn.x + s2n) * sn.y;    // nd[dst] folded into g_ci
        }
        s_src[w][lane] = r;
        s_nrm[w][lane] = nm;
        __syncwarp();
        int cnt = e - base; if (cnt > 32) cnt = 32;
        int ii = 0;
        for (; ii + 4 <= cnt; ii += 4) {
            int   r0 = s_src[w][ii    ], r1 = s_src[w][ii + 1];
            int   r2 = s_src[w][ii + 2], r3 = s_src[w][ii + 3];
            float n0 = s_nrm[w][ii    ], n1 = s_nrm[w][ii + 1];
            float n2 = s_nrm[w][ii + 2], n3 = s_nrm[w][ii + 3];
            float2 h0 = *(const float2*)(g_h + r0 * NH + j2);
            float2 h1 = *(const float2*)(g_h + r1 * NH + j2);
            float2 h2 = *(const float2*)(g_h + r2 * NH + j2);
            float2 h3 = *(const float2*)(g_h + r3 * NH + j2);
            acc.x += n0 * h0.x + n1 * h1.x + n2 * h2.x + n3 * h3.x;
            acc.y += n0 * h0.y + n1 * h1.y + n2 * h2.y + n3 * h3.y;
            ns    += n0 + n1 + n2 + n3;
        }
        for (; ii < cnt; ii++) {
            int   r0 = s_src[w][ii];
            float n0 = s_nrm[w][ii];
            float2 h0 = *(const float2*)(g_h + r0 * NH + j2);
            acc.x += n0 * h0.x;
            acc.y += n0 * h0.y;
            ns    += n0;
        }
        __syncwarp();
    }

    float2 hself = *(const float2*)(g_h + n * NH + j2);   // layer-0 hin == raw
    float ci = g_ci[n];
    float2 ho;
    ho.x = EPSR * hself.x + (acc.x + hself.x * ns) * ci;
    ho.y = EPSR * hself.y + (acc.y + hself.y * ns) * ci;
    *(float2*)(g_h2 + n * NH + j2) = ho;

    // layer-1 gate scalars -> B buffers (no race: layer 0 reads only A)
    float p1 = ho.x * gw_next[j2] + ho.y * gw_next[j2 + 1];
    float p2 = ho.x * gw_next[NH + j2] + ho.y * gw_next[NH + j2 + 1];
#pragma unroll
    for (int off = 16; off > 0; off >>= 1) {
        p1 += __shfl_xor_sync(0xffffffff, p1, off);
        p2 += __shfl_xor_sync(0xffffffff, p2, off);
    }
    if (lane == 0) { g_snB[2 * n] = p1; g_s2[n] = p2; }
}

// layer-1 aggregation fused with classifier + log_softmax
__global__ __launch_bounds__(32 * AGG_WPB) void k_agg1_out(const float* __restrict__ gb,
                                                           const float* __restrict__ W2,
                                                           const float* __restrict__ b2,
                                                           float* __restrict__ out) {
    __shared__ int   s_src[AGG_WPB][32];
    __shared__ float s_nrm[AGG_WPB][32];
    __shared__ float s_h[AGG_WPB][NH];
    __shared__ float sW2t[NH * NC];     // [j][c], c contiguous -> conflict-free
    __shared__ float sb2[NC];

    int tid  = threadIdx.x;
    int w    = tid >> 5;
    int lane = tid & 31;
    int n    = blockIdx.x * AGG_WPB + w;

    for (int idx = tid; idx < NC * NH; idx += 32 * AGG_WPB) {
        int c = idx >> 6, j = idx & 63;
        sW2t[j * NC + c] = W2[idx];
    }
    if (tid < NC) sb2[tid] = b2[tid];
    __syncthreads();
    if (n >= NN) return;

    int b = g_ptr[n];
    int e = g_ptr[n + 1];
    float s2n = g_s2[n] + gb[1];
    float2 acc = make_float2(0.0f, 0.0f);
    float  ns  = 0.0f;
    int j2 = lane * 2;

    for (int base = b; base < e; base += 32) {
        int p = base + lane;
        int r = 0; float nm = 0.0f;
        if (p < e) {
            r = g_srcA[p];
            float2 sn = *(const float2*)(g_snB + 2 * r);
            nm = tanhf(sn.x + s2n) * sn.y;
        }
        s_src[w][lane] = r;
        s_nrm[w][lane] = nm;
        __syncwarp();
        int cnt = e - base; if (cnt > 32) cnt = 32;
        int ii = 0;
        for (; ii + 4 <= cnt; ii += 4) {
            int   r0 = s_src[w][ii    ], r1 = s_src[w][ii + 1];
            int   r2 = s_src[w][ii + 2], r3 = s_src[w][ii + 3];
            float n0 = s_nrm[w][ii    ], n1 = s_nrm[w][ii + 1];
            float n2 = s_nrm[w][ii + 2], n3 = s_nrm[w][ii + 3];
            float2 h0 = *(const float2*)(g_h2 + r0 * NH + j2);
            float2 h1 = *(const float2*)(g_h2 + r1 * NH + j2);
            float2 h2 = *(const float2*)(g_h2 + r2 * NH + j2);
            float2 h3 = *(const float2*)(g_h2 + r3 * NH + j2);
            acc.x += n0 * h0.x + n1 * h1.x + n2 * h2.x + n3 * h3.x;
            acc.y += n0 * h0.y + n1 * h1.y + n2 * h2.y + n3 * h3.y;
            ns    += n0 + n1 + n2 + n3;
        }
        for (; ii < cnt; ii++) {
            int   r0 = s_src[w][ii];
            float n0 = s_nrm[w][ii];
            float2 h0 = *(const float2*)(g_h2 + r0 * NH + j2);
            acc.x += n0 * h0.x;
            acc.y += n0 * h0.y;
            ns    += n0;
        }
        __syncwarp();
    }

    float2 hself = *(const float2*)(g_h2 + n * NH + j2);
    float2 rawv  = *(const float2*)(g_h  + n * NH + j2);
    float ci = g_ci[n];
    float2 ho;
    ho.x = EPSR * rawv.x + (acc.x + hself.x * ns) * ci;
    ho.y = EPSR * rawv.y + (acc.y + hself.y * ns) * ci;
    s_h[w][j2]     = ho.x;
    s_h[w][j2 + 1] = ho.y;
    __syncwarp();

    // classifier: lane handles class c0=lane, c1=lane+32 (if <NC)
    int c0 = lane;
    int c1 = lane + 32;
    float l0 = sb2[c0];
    float l1 = (c1 < NC) ? sb2[c1] : -3.0e38f;
#pragma unroll 8
    for (int j = 0; j < NH; j++) {
        float hv = s_h[w][j];
        l0 += hv * sW2t[j * NC + c0];
        if (c1 < NC) l1 += hv * sW2t[j * NC + c1];
    }
    float m = fmaxf(l0, l1);
#pragma unroll
    for (int off = 16; off > 0; off >>= 1)
        m = fmaxf(m, __shfl_xor_sync(0xffffffff, m, off));
    float s = expf(l0 - m) + ((c1 < NC) ? expf(l1 - m) : 0.0f);
#pragma unroll
    for (int off = 16; off > 0; off >>= 1)
        s += __shfl_xor_sync(0xffffffff, s, off);
    float lse = m + logf(s);
    float* o = out + (size_t)n * NC;
    o[c0] = l0 - lse;
    if (c1 < NC) o[c1] = l1 - lse;
}

extern "C" void kernel_launch(void* const* d_in, const int* in_sizes, int n_in,
                              void* d_out, int out_size) {
    const float* x  = (const float*)d_in[0];
    const int*   ei = (const int*)d_in[1];    // int32 (jax x64 disabled)
    const float* W1 = (const float*)d_in[2];
    const float* b1 = (const float*)d_in[3];
    const float* W2 = (const float*)d_in[4];
    const float* b2 = (const float*)d_in[5];
    const float* gw = (const float*)d_in[6];
    const float* gb = (const float*)d_in[7];
    float* out = (float*)d_out;

    static cudaStream_t sB = nullptr;
    static cudaEvent_t evRoot = nullptr, evJoin = nullptr;
    if (!sB) {
        cudaStreamCreateWithFlags(&sB, cudaStreamNonBlocking);
        cudaEventCreateWithFlags(&evRoot, cudaEventDisableTiming);
        cudaEventCreateWithFlags(&evJoin, cudaEventDisableTiming);
    }

    const int B = 256;

    // fork: GEMM branch on sB, graph-prep branch on the default stream
    cudaEventRecord(evRoot, 0);
    cudaStreamWaitEvent(sB, evRoot, 0);
    k_w1t<<<(NF * NH + B - 1) / B, B, 0, sB>>>(W1);
    k_gemm1<<<(NN + MT - 1) / MT, 256, 0, sB>>>(x, b1, gw);
    cudaEventRecord(evJoin, sB);

    k_zero<<<(NN + B - 1) / B, B>>>();
    k_count<<<(NE + B - 1) / B, B>>>(ei);
    k_scan1<<<NB_SCAN, 256>>>();
    k_scan2<<<1, 256>>>();
    k_scan3<<<NB_SCAN, 256>>>();
    k_bucket<<<(NE + B - 1) / B, B>>>(ei);

    cudaStreamWaitEvent(0, evJoin, 0);   // join before aggregation

    k_agg0<<<(NN + AGG_WPB - 1) / AGG_WPB, 32 * AGG_WPB>>>(gw + 2 * NH, gb);
    k_agg1_out<<<(NN + AGG_WPB - 1) / AGG_WPB, 32 * AGG_WPB>>>(gb, W2, b2, out);
}